// round 1
// baseline (speedup 1.0000x reference)
#include <cuda_runtime.h>
#include <math.h>

#define HIDDEN 64
#define MBATCH 32
#define ATOM   64
#define NUM_RBF 300

#define S_INT   512
#define TAB_ROWS (S_INT + 3)            // 515 samples, grid point n = (row-1)*h
#define H_STEP  (10.0f / (float)S_INT)  // 0.01953125
#define INV_H   ((float)S_INT / 10.0f)  // 51.2

// device scratch (no allocations allowed)
__device__ __align__(16) float g_table[TAB_ROWS * HIDDEN];
__device__ __align__(16) float g_v1[MBATCH * ATOM * HIDDEN];
__device__ __align__(16) float g_W2t[HIDDEN * HIDDEN];
__device__ __align__(16) float g_W3t[HIDDEN * HIDDEN];

__device__ __forceinline__ float softplus_f(float v) {
    // matches jax.nn.softplus = logaddexp(v, 0)
    return fmaxf(v, 0.0f) + log1pf(expf(-fabsf(v)));
}

// ---------------------------------------------------------------------------
// Prep kernel: blocks [0,129) build the h(d) table (4 samples each),
// blocks [129,161) compute v1 = x@W1^T + b1 (one m each),
// blocks 161/162 transpose W2/W3.
// ---------------------------------------------------------------------------
#define PREP_TAB_BLOCKS 129
#define PREP_BLOCKS 163
#define PREP_SMEM ((64*301 + 64*65 + 300 + 64 + 4) * 4)

__global__ void __launch_bounds__(64) prep_kernel(
    const float* __restrict__ x,  const float* __restrict__ W1, const float* __restrict__ b1,
    const float* __restrict__ W2, const float* __restrict__ W3,
    const float* __restrict__ Wd1, const float* __restrict__ bd1,
    const float* __restrict__ Wd2, const float* __restrict__ bd2)
{
    extern __shared__ float sh[];
    const int tid = threadIdx.x;
    const int b = blockIdx.x;

    if (b < PREP_TAB_BLOCKS) {
        float* Wd1_s = sh;                  // 64 x 301 (padded, conflict-free)
        float* Wd2_s = sh + 64 * 301;       // 64 x 65
        float* rbf_s = Wd2_s + 64 * 65;     // 300
        float* g_s   = rbf_s + 300;         // 64

        for (int idx = tid; idx < 64 * NUM_RBF; idx += 64) {
            int c = idx / NUM_RBF;
            int r = idx - c * NUM_RBF;
            Wd1_s[c * 301 + r] = Wd1[idx];
        }
        for (int idx = tid; idx < 64 * 64; idx += 64) {
            int c = idx >> 6, k = idx & 63;
            Wd2_s[c * 65 + k] = Wd2[idx];
        }
        const float bd1c = bd1[tid];
        const float bd2c = bd2[tid];
        __syncthreads();

        for (int q = 0; q < 4; q++) {
            int s = b * 4 + q;
            float d = (float)(s - 1) * H_STEP;
            for (int r = tid; r < NUM_RBF; r += 64) {
                float u = d - 0.1f * (float)r;
                rbf_s[r] = __expf(-10.0f * u * u);
            }
            __syncthreads();
            float p = bd1c;
            const float* wrow = Wd1_s + tid * 301;
            #pragma unroll 4
            for (int r = 0; r < NUM_RBF; r++) p = fmaf(wrow[r], rbf_s[r], p);
            g_s[tid] = softplus_f(p);
            __syncthreads();
            float qv = bd2c;
            const float* w2row = Wd2_s + tid * 65;
            #pragma unroll 8
            for (int k = 0; k < 64; k++) qv = fmaf(w2row[k], g_s[k], qv);
            if (s < TAB_ROWS) g_table[s * 64 + tid] = softplus_f(qv);
            __syncthreads();
        }
    } else if (b < PREP_TAB_BLOCKS + MBATCH) {
        const int m = b - PREP_TAB_BLOCKS;
        float* W1_s = sh;                // 64 x 65 padded
        float* x_s  = sh + 64 * 65;      // 64 x 65 padded
        for (int idx = tid; idx < 4096; idx += 64) {
            int r0 = idx >> 6, c0 = idx & 63;
            W1_s[r0 * 65 + c0] = W1[idx];
            x_s[r0 * 65 + c0]  = x[m * 4096 + idx];
        }
        __syncthreads();
        float acc[64];
        #pragma unroll
        for (int o = 0; o < 64; o++) acc[o] = b1[o];
        const float* xrow = x_s + tid * 65;   // thread = source atom i
        for (int c = 0; c < 64; c++) {
            float xv = xrow[c];
            #pragma unroll
            for (int o = 0; o < 64; o++) acc[o] = fmaf(W1_s[o * 65 + c], xv, acc[o]);
        }
        float* vout = g_v1 + (m * 64 + tid) * 64;
        #pragma unroll
        for (int o = 0; o < 64; o++) vout[o] = acc[o];
    } else {
        const float* src = (b == PREP_TAB_BLOCKS + MBATCH) ? W2 : W3;
        float* dst = (b == PREP_TAB_BLOCKS + MBATCH) ? g_W2t : g_W3t;
        for (int idx = tid; idx < 4096; idx += 64) {
            int c = idx >> 6, o = idx & 63;
            dst[idx] = src[o * 64 + c];   // dst[c][o] = src[o][c]
        }
    }
}

// ---------------------------------------------------------------------------
// Main kernel: 128 blocks = 32 m x 4 j-groups (16 j each), 256 threads.
// Thread (jj, c4) owns destination atom j0+jj, channels 4*c4..+3.
// out_pair[m,j,c] = sum_i v1[m,i,c] * h_c(dist[m,i,j]), h via cubic interp
// of the shared table; then fused sp(W2)+W3 output MLP + residual.
// ---------------------------------------------------------------------------
#define MAIN_SMEM ((TAB_ROWS*64 + 4096 + 4096 + 4096 + 4096 + 1024 + 1024 + 64 + 64 + 1024) * 4)

__global__ void __launch_bounds__(256) main_kernel(
    const float* __restrict__ x, const float* __restrict__ dist,
    const float* __restrict__ b2, const float* __restrict__ b3,
    float* __restrict__ out)
{
    extern __shared__ float sh[];
    float* TAB  = sh;                       // 515*64
    float* V1   = TAB + TAB_ROWS * 64;      // 4096
    float* W4   = V1 + 4096;                // 1024 pairs * float4
    float* W2T  = W4 + 4096;                // 4096
    float* W3T  = W2T + 4096;               // 4096
    float* PAIR = W3T + 4096;               // 16*64
    float* V2   = PAIR + 1024;              // 16*64
    float* B2   = V2 + 1024;                // 64
    float* B3   = B2 + 64;                  // 64
    int*   KK   = (int*)(B3 + 64);          // 1024

    const int tid = threadIdx.x;
    const int m  = blockIdx.x >> 2;
    const int j0 = (blockIdx.x & 3) * 16;

    // cooperative shared loads
    {
        const float4* ts = (const float4*)g_table;
        float4* td = (float4*)TAB;
        for (int idx = tid; idx < (TAB_ROWS * 64) / 4; idx += 256) td[idx] = ts[idx];
        const float4* vs = (const float4*)(g_v1 + m * 4096);
        float4* vd = (float4*)V1;
        const float4* w2s = (const float4*)g_W2t;
        const float4* w3s = (const float4*)g_W3t;
        float4* w2d = (float4*)W2T;
        float4* w3d = (float4*)W3T;
        for (int idx = tid; idx < 1024; idx += 256) {
            vd[idx] = vs[idx];
            w2d[idx] = w2s[idx];
            w3d[idx] = w3s[idx];
        }
        if (tid < 64) { B2[tid] = b2[tid]; B3[tid] = b3[tid]; }
    }
    // per-pair interpolation weights (Lagrange cubic, nodes -1,0,1,2)
    for (int p = tid; p < 1024; p += 256) {
        int i = p >> 4, jj = p & 15;
        float d = dist[(m * 64 + i) * 64 + j0 + jj];
        float t = d * INV_H;
        int k = (int)t;
        if (k > S_INT - 1) k = S_INT - 1;
        if (k < 0) k = 0;
        float u = t - (float)k;
        float um1 = u - 1.0f, um2 = u - 2.0f, up1 = u + 1.0f;
        float4 w;
        w.x = -u * um1 * um2 * (1.0f / 6.0f);
        w.y =  up1 * um1 * um2 * 0.5f;
        w.z = -up1 * u * um2 * 0.5f;
        w.w =  up1 * u * um1 * (1.0f / 6.0f);
        ((float4*)W4)[p] = w;
        KK[p] = k;
    }
    __syncthreads();

    const int jj   = tid >> 4;        // 0..15 destination atom within group
    const int cidx = tid & 15;        // float4 channel group 0..15
    const int c4   = cidx << 2;

    float4 acc = make_float4(0.f, 0.f, 0.f, 0.f);
    const float4* TABv = (const float4*)TAB;
    const float4* W4v  = (const float4*)W4;
    const float4* V1v  = (const float4*)V1;

    #pragma unroll 4
    for (int i = 0; i < 64; i++) {
        float4 w = W4v[i * 16 + jj];
        int k = KK[i * 16 + jj];
        const float4* trow = TABv + k * 16 + cidx;
        float4 t0 = trow[0];
        float4 t1 = trow[16];
        float4 t2 = trow[32];
        float4 t3 = trow[48];
        float4 vv = V1v[i * 16 + cidx];
        float hx = fmaf(w.x, t0.x, fmaf(w.y, t1.x, fmaf(w.z, t2.x, w.w * t3.x)));
        float hy = fmaf(w.x, t0.y, fmaf(w.y, t1.y, fmaf(w.z, t2.y, w.w * t3.y)));
        float hz = fmaf(w.x, t0.z, fmaf(w.y, t1.z, fmaf(w.z, t2.z, w.w * t3.z)));
        float hw = fmaf(w.x, t0.w, fmaf(w.y, t1.w, fmaf(w.z, t2.w, w.w * t3.w)));
        acc.x = fmaf(vv.x, hx, acc.x);
        acc.y = fmaf(vv.y, hy, acc.y);
        acc.z = fmaf(vv.z, hz, acc.z);
        acc.w = fmaf(vv.w, hw, acc.w);
    }
    ((float4*)PAIR)[jj * 16 + cidx] = acc;
    __syncthreads();

    // layer 2: v2 = softplus(PAIR @ W2^T + b2), using W2T[c][o]
    {
        float4 a = make_float4(B2[c4], B2[c4 + 1], B2[c4 + 2], B2[c4 + 3]);
        const float* pr = PAIR + jj * 64;
        const float4* w2 = (const float4*)W2T;
        #pragma unroll 8
        for (int c = 0; c < 64; c++) {
            float pv = pr[c];
            float4 wv = w2[c * 16 + cidx];
            a.x = fmaf(pv, wv.x, a.x);
            a.y = fmaf(pv, wv.y, a.y);
            a.z = fmaf(pv, wv.z, a.z);
            a.w = fmaf(pv, wv.w, a.w);
        }
        a.x = softplus_f(a.x);
        a.y = softplus_f(a.y);
        a.z = softplus_f(a.z);
        a.w = softplus_f(a.w);
        ((float4*)(V2 + jj * 64))[cidx] = a;
    }
    __syncthreads();

    // layer 3 + residual: out = x + V2 @ W3^T + b3
    {
        float4 a = make_float4(B3[c4], B3[c4 + 1], B3[c4 + 2], B3[c4 + 3]);
        const float* pr = V2 + jj * 64;
        const float4* w3 = (const float4*)W3T;
        #pragma unroll 8
        for (int c = 0; c < 64; c++) {
            float pv = pr[c];
            float4 wv = w3[c * 16 + cidx];
            a.x = fmaf(pv, wv.x, a.x);
            a.y = fmaf(pv, wv.y, a.y);
            a.z = fmaf(pv, wv.z, a.z);
            a.w = fmaf(pv, wv.w, a.w);
        }
        int gidx = (m * 64 + j0 + jj) * 64 + c4;
        float4 xv = *(const float4*)(x + gidx);
        a.x += xv.x; a.y += xv.y; a.z += xv.z; a.w += xv.w;
        *(float4*)(out + gidx) = a;
    }
}

extern "C" void kernel_launch(void* const* d_in, const int* in_sizes, int n_in,
                              void* d_out, int out_size) {
    const float* x   = (const float*)d_in[0];
    const float* dist= (const float*)d_in[1];
    const float* W1  = (const float*)d_in[2];
    const float* b1  = (const float*)d_in[3];
    const float* W2  = (const float*)d_in[4];
    const float* b2  = (const float*)d_in[5];
    const float* W3  = (const float*)d_in[6];
    const float* b3  = (const float*)d_in[7];
    const float* Wd1 = (const float*)d_in[8];
    const float* bd1 = (const float*)d_in[9];
    const float* Wd2 = (const float*)d_in[10];
    const float* bd2 = (const float*)d_in[11];
    float* out = (float*)d_out;
    (void)in_sizes; (void)n_in; (void)out_size;

    cudaFuncSetAttribute(prep_kernel, cudaFuncAttributeMaxDynamicSharedMemorySize, PREP_SMEM);
    cudaFuncSetAttribute(main_kernel, cudaFuncAttributeMaxDynamicSharedMemorySize, MAIN_SMEM);

    prep_kernel<<<PREP_BLOCKS, 64, PREP_SMEM>>>(x, W1, b1, W2, W3, Wd1, bd1, Wd2, bd2);
    main_kernel<<<128, 256, MAIN_SMEM>>>(x, dist, b2, b3, out);
}

// round 2
// speedup vs baseline: 2.7024x; 2.7024x over previous
#include <cuda_runtime.h>
#include <math.h>

#define HIDDEN 64
#define MBATCH 32
#define ATOM   64
#define NUM_RBF 300

#define S_INT   512
#define TAB_ROWS 515                    // row s holds h((s-1)*H_STEP)
#define H_STEP  (10.0f / 512.0f)
#define INV_H   51.2f

// device scratch (no allocations allowed)
__device__ __align__(16) float g_table[TAB_ROWS * HIDDEN];
__device__ __align__(16) float g_v1[MBATCH * ATOM * HIDDEN];
__device__ __align__(16) float g_W2t[HIDDEN * HIDDEN];
__device__ __align__(16) float g_W3t[HIDDEN * HIDDEN];

__device__ __forceinline__ float softplus_f(float v) {
    // matches jax.nn.softplus = logaddexp(v, 0)
    return fmaxf(v, 0.0f) + log1pf(expf(-fabsf(v)));
}

// ---------------------------------------------------------------------------
// Prep kernel, 512 threads/block:
//   blocks [0,65):    h(d) table, 8 samples per block, thread=(sample,channel)
//   blocks [65,129):  v1 = x@W1^T + b1, block=(m, i-half), float4 reg blocking
//   block 129:        transpose W2, W3 into g_W2t/g_W3t
// ---------------------------------------------------------------------------
#define TAB_BLOCKS 65
#define V1_BLOCKS  64
#define PREP_BLOCKS (TAB_BLOCKS + V1_BLOCKS + 1)
#define PREP_SMEM ((64*301 + 64*65 + 8*304 + 8*64) * 4)   // 105472 B

__global__ void __launch_bounds__(512) prep_kernel(
    const float* __restrict__ x,  const float* __restrict__ W1, const float* __restrict__ b1,
    const float* __restrict__ W2, const float* __restrict__ W3,
    const float* __restrict__ Wd1, const float* __restrict__ bd1,
    const float* __restrict__ Wd2, const float* __restrict__ bd2)
{
    extern __shared__ float sh[];
    const int tid = threadIdx.x;
    const int b = blockIdx.x;

    if (b < TAB_BLOCKS) {
        float* Wd1_s = sh;                   // 64 x 301 (padded)
        float* Wd2_s = Wd1_s + 64 * 301;     // 64 x 65  (padded)
        float* rbf_s = Wd2_s + 64 * 65;      // 8 x 304
        float* g_s   = rbf_s + 8 * 304;      // 8 x 64

        for (int idx = tid; idx < 64 * NUM_RBF; idx += 512) {
            int cc = idx / NUM_RBF;
            int r  = idx - cc * NUM_RBF;
            Wd1_s[cc * 301 + r] = Wd1[idx];
        }
        for (int idx = tid; idx < 4096; idx += 512) {
            Wd2_s[(idx >> 6) * 65 + (idx & 63)] = Wd2[idx];
        }
        const int s0 = b * 8;
        for (int idx = tid; idx < 8 * NUM_RBF; idx += 512) {
            int qq = idx / NUM_RBF;
            int r  = idx - qq * NUM_RBF;
            float dd = (float)(s0 + qq - 1) * H_STEP;
            float u = dd - 0.1f * (float)r;
            rbf_s[qq * 304 + r] = __expf(-10.0f * u * u);
        }
        __syncthreads();

        const int q = tid >> 6;              // sample within block
        const int c = tid & 63;              // channel
        const int s = s0 + q;
        const float d = (float)(s - 1) * H_STEP;
        // only RBFs within |d - 0.1r| <= 1.5 contribute (> 1.7e-10)
        int rlo = (int)ceilf((d - 1.5f) * 10.0f); if (rlo < 0) rlo = 0;
        int rhi = (int)floorf((d + 1.5f) * 10.0f); if (rhi > NUM_RBF - 1) rhi = NUM_RBF - 1;
        float p = bd1[c];
        const float* wrow = Wd1_s + c * 301;
        const float* rrow = rbf_s + q * 304;
        for (int r = rlo; r <= rhi; r++) p = fmaf(wrow[r], rrow[r], p);
        g_s[q * 64 + c] = softplus_f(p);
        __syncthreads();

        float qv = bd2[c];
        const float* w2row = Wd2_s + c * 65;
        const float* gg = g_s + q * 64;
        #pragma unroll 8
        for (int k = 0; k < 64; k++) qv = fmaf(w2row[k], gg[k], qv);
        if (s < TAB_ROWS) g_table[s * 64 + c] = softplus_f(qv);
    } else if (b < TAB_BLOCKS + V1_BLOCKS) {
        const int v = b - TAB_BLOCKS;
        const int m = v >> 1, half = v & 1;
        float* W1p = sh;                 // 64 x 68 (padded, float4-aligned rows)
        float* xp  = sh + 64 * 68;       // 32 x 68

        for (int idx = tid; idx < 4096; idx += 512) {
            int o = idx >> 6, c = idx & 63;
            W1p[o * 68 + c] = W1[idx];
        }
        for (int idx = tid; idx < 2048; idx += 512) {
            int ii = idx >> 6, c = idx & 63;
            xp[ii * 68 + c] = x[m * 4096 + (half * 32 + ii) * 64 + c];
        }
        __syncthreads();

        const int ii = tid & 31;         // warp-uniform oh -> broadcast W loads
        const int oh = tid >> 5;         // 0..15, 4 outputs each
        float4 acc = make_float4(0.f, 0.f, 0.f, 0.f);
        const float* xr = xp + ii * 68;
        const float* wr = W1p + oh * 4 * 68;
        #pragma unroll
        for (int c4 = 0; c4 < 16; c4++) {
            float4 xv = *(const float4*)(xr + c4 * 4);
            float4 w0 = *(const float4*)(wr + 0 * 68 + c4 * 4);
            float4 w1 = *(const float4*)(wr + 1 * 68 + c4 * 4);
            float4 w2 = *(const float4*)(wr + 2 * 68 + c4 * 4);
            float4 w3 = *(const float4*)(wr + 3 * 68 + c4 * 4);
            acc.x = fmaf(xv.x, w0.x, fmaf(xv.y, w0.y, fmaf(xv.z, w0.z, fmaf(xv.w, w0.w, acc.x))));
            acc.y = fmaf(xv.x, w1.x, fmaf(xv.y, w1.y, fmaf(xv.z, w1.z, fmaf(xv.w, w1.w, acc.y))));
            acc.z = fmaf(xv.x, w2.x, fmaf(xv.y, w2.y, fmaf(xv.z, w2.z, fmaf(xv.w, w2.w, acc.z))));
            acc.w = fmaf(xv.x, w3.x, fmaf(xv.y, w3.y, fmaf(xv.z, w3.z, fmaf(xv.w, w3.w, acc.w))));
        }
        float4 bv = *(const float4*)(b1 + oh * 4);
        acc.x += bv.x; acc.y += bv.y; acc.z += bv.z; acc.w += bv.w;
        const int i = half * 32 + ii;
        *(float4*)(g_v1 + (m * 64 + i) * 64 + oh * 4) = acc;
    } else {
        for (int idx = tid; idx < 8192; idx += 512) {
            const float* src = (idx < 4096) ? W2 : W3;
            float* dst = (idx < 4096) ? g_W2t : g_W3t;
            int e = idx & 4095;
            int c = e >> 6, o = e & 63;
            dst[e] = src[o * 64 + c];    // dst[c][o]
        }
    }
}

// ---------------------------------------------------------------------------
// Main kernel: 128 blocks = (m, j-group of 16), 1024 threads (32 warps).
// thread = (ihalf 0..3, jj 0..15, cidx 0..15); 4-way split of the i-sum,
// reduced via smem. Epilogue weights prefetched to registers, staged into
// the freed PART/W4 smem regions.
// ---------------------------------------------------------------------------
#define MAIN_SMEM ((32960 + 4096 + 4096 + 4096 + 1024 + 1024 + 64 + 64 + 1024) * 4)  // 193792 B

__global__ void __launch_bounds__(1024) main_kernel(
    const float* __restrict__ x, const float* __restrict__ dist,
    const float* __restrict__ b2, const float* __restrict__ b3,
    float* __restrict__ out)
{
    extern __shared__ float sh[];
    float* TAB  = sh;                    // 515*64 = 32960
    float* V1s  = TAB + 32960;           // 4096
    float* W4s  = V1s + 4096;            // 4096 pair-weights -> reused as W3T
    float* PART = W4s + 4096;            // 4096 partials     -> reused as W2T
    float* PAIR = PART + 4096;           // 1024
    float* V2s  = PAIR + 1024;           // 1024
    float* B2s  = V2s + 1024;            // 64
    float* B3s  = B2s + 64;              // 64
    int*   KKs  = (int*)(B3s + 64);      // 1024

    const int tid = threadIdx.x;
    const int m  = blockIdx.x >> 2;
    const int j0 = (blockIdx.x & 3) << 4;

    // prefetch epilogue weights into registers (stored to smem after reduce)
    const float4 w2reg = ((const float4*)g_W2t)[tid];
    const float4 w3reg = ((const float4*)g_W3t)[tid];

    // stage table + v1 + biases
    {
        const float4* ts = (const float4*)g_table;
        float4* td = (float4*)TAB;
        #pragma unroll
        for (int r = 0; r < 8; r++) td[tid + r * 1024] = ts[tid + r * 1024];
        if (tid < 48) td[8192 + tid] = ts[8192 + tid];
        ((float4*)V1s)[tid] = ((const float4*)(g_v1 + m * 4096))[tid];
        if (tid < 64) B2s[tid] = b2[tid];
        else if (tid < 128) B3s[tid - 64] = b3[tid - 64];
    }
    // per-pair cubic Lagrange weights (nodes -1,0,1,2), one pair per thread
    {
        const int i = tid >> 4, jj = tid & 15;
        float d = dist[(m * 64 + i) * 64 + j0 + jj];
        float t = d * INV_H;
        int k = (int)t;
        k = min(max(k, 0), S_INT - 1);
        float u = t - (float)k;
        float um1 = u - 1.0f, um2 = u - 2.0f, up1 = u + 1.0f;
        float4 w;
        w.x = -u * um1 * um2 * (1.0f / 6.0f);
        w.y =  up1 * um1 * um2 * 0.5f;
        w.z = -up1 * u * um2 * 0.5f;
        w.w =  up1 * u * um1 * (1.0f / 6.0f);
        ((float4*)W4s)[tid] = w;
        KKs[tid] = k;
    }
    __syncthreads();

    const int ihalf = tid >> 8;          // 0..3
    const int jj    = (tid >> 4) & 15;   // destination atom within group
    const int cidx  = tid & 15;          // float4 channel group

    float4 acc = make_float4(0.f, 0.f, 0.f, 0.f);
    const float4* TABv = (const float4*)TAB;
    const float4* W4v  = (const float4*)W4s;
    const float4* V1v  = (const float4*)V1s;
    const int ibase = ihalf << 4;

    #pragma unroll 4
    for (int ii = 0; ii < 16; ii++) {
        const int i = ibase + ii;
        float4 w = W4v[i * 16 + jj];
        int k = KKs[i * 16 + jj];
        const float4* trow = TABv + k * 16 + cidx;
        float4 t0 = trow[0];
        float4 t1 = trow[16];
        float4 t2 = trow[32];
        float4 t3 = trow[48];
        float4 vv = V1v[i * 16 + cidx];
        float hx = fmaf(w.x, t0.x, fmaf(w.y, t1.x, fmaf(w.z, t2.x, w.w * t3.x)));
        float hy = fmaf(w.x, t0.y, fmaf(w.y, t1.y, fmaf(w.z, t2.y, w.w * t3.y)));
        float hz = fmaf(w.x, t0.z, fmaf(w.y, t1.z, fmaf(w.z, t2.z, w.w * t3.z)));
        float hw = fmaf(w.x, t0.w, fmaf(w.y, t1.w, fmaf(w.z, t2.w, w.w * t3.w)));
        acc.x = fmaf(vv.x, hx, acc.x);
        acc.y = fmaf(vv.y, hy, acc.y);
        acc.z = fmaf(vv.z, hz, acc.z);
        acc.w = fmaf(vv.w, hw, acc.w);
    }
    ((float4*)PART)[(ihalf << 8) + (jj << 4) + cidx] = acc;
    __syncthreads();

    if (tid < 256) {
        float4 a0 = ((float4*)PART)[tid];
        float4 a1 = ((float4*)PART)[256 + tid];
        float4 a2 = ((float4*)PART)[512 + tid];
        float4 a3 = ((float4*)PART)[768 + tid];
        float4 s4;
        s4.x = (a0.x + a1.x) + (a2.x + a3.x);
        s4.y = (a0.y + a1.y) + (a2.y + a3.y);
        s4.z = (a0.z + a1.z) + (a2.z + a3.z);
        s4.w = (a0.w + a1.w) + (a2.w + a3.w);
        ((float4*)PAIR)[tid] = s4;
    }
    __syncthreads();

    // stage epilogue weights into freed regions
    ((float4*)PART)[tid] = w2reg;   // W2T [c][o]
    ((float4*)W4s)[tid]  = w3reg;   // W3T [c][o]
    __syncthreads();

    const int jj2 = tid >> 6;   // 0..15
    const int o   = tid & 63;

    // layer 2: v2 = softplus(PAIR @ W2^T + b2)
    {
        float a = B2s[o];
        const float* pr = PAIR + jj2 * 64;
        #pragma unroll 8
        for (int c = 0; c < 64; c++) a = fmaf(pr[c], PART[c * 64 + o], a);
        V2s[jj2 * 64 + o] = softplus_f(a);
    }
    __syncthreads();

    // layer 3 + residual
    {
        float a = B3s[o];
        const float* pr = V2s + jj2 * 64;
        #pragma unroll 8
        for (int c = 0; c < 64; c++) a = fmaf(pr[c], W4s[c * 64 + o], a);
        const int gidx = (m * 64 + j0 + jj2) * 64 + o;
        out[gidx] = x[gidx] + a;
    }
}

extern "C" void kernel_launch(void* const* d_in, const int* in_sizes, int n_in,
                              void* d_out, int out_size) {
    const float* x   = (const float*)d_in[0];
    const float* dist= (const float*)d_in[1];
    const float* W1  = (const float*)d_in[2];
    const float* b1  = (const float*)d_in[3];
    const float* W2  = (const float*)d_in[4];
    const float* b2  = (const float*)d_in[5];
    const float* W3  = (const float*)d_in[6];
    const float* b3  = (const float*)d_in[7];
    const float* Wd1 = (const float*)d_in[8];
    const float* bd1 = (const float*)d_in[9];
    const float* Wd2 = (const float*)d_in[10];
    const float* bd2 = (const float*)d_in[11];
    float* out = (float*)d_out;
    (void)in_sizes; (void)n_in; (void)out_size;

    cudaFuncSetAttribute(prep_kernel, cudaFuncAttributeMaxDynamicSharedMemorySize, PREP_SMEM);
    cudaFuncSetAttribute(main_kernel, cudaFuncAttributeMaxDynamicSharedMemorySize, MAIN_SMEM);

    prep_kernel<<<PREP_BLOCKS, 512, PREP_SMEM>>>(x, W1, b1, W2, W3, Wd1, bd1, Wd2, bd2);
    main_kernel<<<128, 1024, MAIN_SMEM>>>(x, dist, b2, b3, out);
}